// round 2
// baseline (speedup 1.0000x reference)
#include <cuda_runtime.h>
#include <cuda_bf16.h>
#include <math.h>

// ---------------- constants ----------------
#define BATCH   2
#define SEQ     4096
#define ROWS    (BATCH*SEQ)        // 8192
#define DMODEL  2048
#define DSTATE  64
#define DHEAD   64
#define NHEADS  32
#define CHUNK   64
#define NCHUNK  (SEQ/CHUNK)        // 64
#define CONVD   6144               // D_MODEL + 2*N_HEADS*D_STATE
#define ZXB_LD  8192               // cols we compute of zxbcdt (dt cols unused)
#define RMS_EPS 1.1920929e-07f

// ---------------- scratch (device globals: allocation-free) ----------------
__device__ float g_zxbc[(size_t)ROWS * ZXB_LD];   // [8192, 8192]  z | xBC(pre-conv)
__device__ float g_xbca[(size_t)ROWS * CONVD];    // [8192, 6144]  silu(conv(xBC))
__device__ float g_y   [(size_t)ROWS * DMODEL];   // Y_diag then reused as Y
__device__ float g_yn  [(size_t)ROWS * DMODEL];   // gated + rmsnormed
__device__ float g_cs  [(size_t)BATCH*NHEADS*NCHUNK*DSTATE]; // chunk states
__device__ float g_prev[(size_t)BATCH*NHEADS*NCHUNK*DSTATE]; // scanned prev states

// ---------------- tf32 helpers ----------------
__device__ __forceinline__ unsigned f2tf(float x) {
    unsigned r; asm("cvt.rna.tf32.f32 %0, %1;" : "=r"(r) : "f"(x)); return r;
}

// ============================================================================
// GEMM: C[M,N] = A[M,K] * B[N,K]^T, row-major fp32, tf32 tensor cores.
// Block 128x128, K-tile 32, 256 threads = 8 warps (2m x 4n), warp tile 64x32,
// mma m16n8k8 grid 4x4 per warp. Register-staged prefetch pipeline: next
// K-tile's global loads issue before the current tile's compute, so DRAM/L2
// latency overlaps the 64-MMA compute phase.
// ============================================================================
__global__ __launch_bounds__(256, 1) void gemm_tn_tf32(
    const float* __restrict__ A, const float* __restrict__ B,
    float* __restrict__ C, int M, int N, int K)
{
    __shared__ __align__(16) unsigned As[128 * 36];
    __shared__ __align__(16) unsigned Bs[128 * 36];

    const int tid  = threadIdx.x;
    const int row0 = blockIdx.y * 128;
    const int col0 = blockIdx.x * 128;
    const int warp = tid >> 5, lane = tid & 31;
    const int wm = warp >> 2, wn = warp & 3;          // 2 x 4 warp grid
    const int g  = lane >> 2, tg = lane & 3;          // mma group / thread-in-group

    float acc[4][4][4];
#pragma unroll
    for (int i = 0; i < 4; i++)
#pragma unroll
        for (int j = 0; j < 4; j++)
#pragma unroll
            for (int k = 0; k < 4; k++) acc[i][j][k] = 0.f;

    const int lr = tid >> 3;        // 0..31 row-in-step
    const int lc = (tid & 7) * 4;   // float4 col

    const float* Abase = A + (size_t)(row0 + lr) * K + lc;
    const float* Bbase = B + (size_t)(col0 + lr) * K + lc;
    const size_t strideA = (size_t)32 * K;

    float4 ra[4], rb[4];
#pragma unroll
    for (int s = 0; s < 4; s++) {
        ra[s] = *(const float4*)(Abase + s * strideA);
        rb[s] = *(const float4*)(Bbase + s * strideA);
    }

    for (int k0 = 0; k0 < K; k0 += 32) {
        __syncthreads();
#pragma unroll
        for (int s = 0; s < 4; s++) {
            int rr = s * 32 + lr;
            unsigned* da = &As[rr * 36 + lc];
            da[0] = f2tf(ra[s].x); da[1] = f2tf(ra[s].y); da[2] = f2tf(ra[s].z); da[3] = f2tf(ra[s].w);
            unsigned* db = &Bs[rr * 36 + lc];
            db[0] = f2tf(rb[s].x); db[1] = f2tf(rb[s].y); db[2] = f2tf(rb[s].z); db[3] = f2tf(rb[s].w);
        }
        __syncthreads();

        // Prefetch next K-tile while this tile computes.
        if (k0 + 32 < K) {
#pragma unroll
            for (int s = 0; s < 4; s++) {
                ra[s] = *(const float4*)(Abase + (k0 + 32) + s * strideA);
                rb[s] = *(const float4*)(Bbase + (k0 + 32) + s * strideA);
            }
        }

#pragma unroll
        for (int kk = 0; kk < 32; kk += 8) {
            unsigned a[4][4], bf[4][2];
#pragma unroll
            for (int mt = 0; mt < 4; mt++) {
                int r = wm * 64 + mt * 16 + g;
                a[mt][0] = As[r * 36 + kk + tg];
                a[mt][1] = As[(r + 8) * 36 + kk + tg];
                a[mt][2] = As[r * 36 + kk + tg + 4];
                a[mt][3] = As[(r + 8) * 36 + kk + tg + 4];
            }
#pragma unroll
            for (int nt = 0; nt < 4; nt++) {
                int cn = wn * 32 + nt * 8 + g;
                bf[nt][0] = Bs[cn * 36 + kk + tg];
                bf[nt][1] = Bs[cn * 36 + kk + tg + 4];
            }
#pragma unroll
            for (int mt = 0; mt < 4; mt++)
#pragma unroll
                for (int nt = 0; nt < 4; nt++)
                    asm volatile(
                        "mma.sync.aligned.m16n8k8.row.col.f32.tf32.tf32.f32 "
                        "{%0,%1,%2,%3}, {%4,%5,%6,%7}, {%8,%9}, {%0,%1,%2,%3};"
                        : "+f"(acc[mt][nt][0]), "+f"(acc[mt][nt][1]),
                          "+f"(acc[mt][nt][2]), "+f"(acc[mt][nt][3])
                        : "r"(a[mt][0]), "r"(a[mt][1]), "r"(a[mt][2]), "r"(a[mt][3]),
                          "r"(bf[nt][0]), "r"(bf[nt][1]));
        }
    }

#pragma unroll
    for (int mt = 0; mt < 4; mt++) {
        int r = row0 + wm * 64 + mt * 16 + g;
#pragma unroll
        for (int nt = 0; nt < 4; nt++) {
            int cc = col0 + wn * 32 + nt * 8 + 2 * tg;
            *(float2*)&C[(size_t)r * N + cc]       = make_float2(acc[mt][nt][0], acc[mt][nt][1]);
            *(float2*)&C[(size_t)(r + 8) * N + cc] = make_float2(acc[mt][nt][2], acc[mt][nt][3]);
        }
    }
}

// ============================================================================
// Depthwise conv(3) + bias + SiLU over xBC channels (cols 2048..8191 of zxbc)
// ============================================================================
__global__ void conv_silu_kernel(const float* __restrict__ zxbc,
                                 const float* __restrict__ cw,
                                 const float* __restrict__ cb,
                                 float* __restrict__ out)
{
    int ch = blockIdx.x * blockDim.x + threadIdx.x;  // 0..6143
    int r  = blockIdx.y;                             // 0..8191
    if (ch >= CONVD) return;
    int l = r & (SEQ - 1);
    const float* col = zxbc + DMODEL + ch;
    float xm = (l > 0)       ? col[(size_t)(r - 1) * ZXB_LD] : 0.f;
    float x0 =                 col[(size_t)r       * ZXB_LD];
    float xp = (l < SEQ - 1) ? col[(size_t)(r + 1) * ZXB_LD] : 0.f;
    float v = fmaf(cw[ch * 3], xm, fmaf(cw[ch * 3 + 1], x0, fmaf(cw[ch * 3 + 2], xp, cb[ch])));
    out[(size_t)r * CONVD + ch] = v / (1.f + expf(-v));
}

// ============================================================================
// Per-chunk SSD: G = (C B^T) .* causal ; Y_diag = G x ; cs[n] = sum_l x[l,n]B[l,n]
// One block per (b,h,c) = 4096 blocks, 256 threads, 48KB shared.
// ============================================================================
__global__ __launch_bounds__(256) void ssd_chunk_kernel(const float* __restrict__ xbca,
                                                        float* __restrict__ ydiag,
                                                        float* __restrict__ cs)
{
    __shared__ float Bs[64][64];
    __shared__ float Cs[64][64];   // reused for x after G is computed
    __shared__ float Gs[64][64];

    int bid = blockIdx.x;
    int c  = bid & 63;
    int bh = bid >> 6;
    int h  = bh & 31;
    int b  = bh >> 5;
    size_t row0 = (size_t)(b * SEQ + c * CHUNK) * CONVD;
    int tid = threadIdx.x;

    for (int i = tid; i < 64 * 16; i += 256) {
        int l = i >> 4, q = (i & 15) * 4;
        *(float4*)&Bs[l][q] = *(const float4*)&xbca[row0 + (size_t)l * CONVD + DMODEL + h * 64 + q];
        *(float4*)&Cs[l][q] = *(const float4*)&xbca[row0 + (size_t)l * CONVD + 2 * DMODEL + h * 64 + q];
    }
    __syncthreads();

    int l  = tid >> 2;
    int m0 = tid & 3;
    for (int m = m0; m <= l; m += 4) {
        float a = 0.f;
#pragma unroll 8
        for (int n = 0; n < 64; n++) a += Cs[l][n] * Bs[m][n];
        Gs[l][m] = a;
    }
    __syncthreads();

    // load x over Cs
    for (int i = tid; i < 64 * 16; i += 256) {
        int ll = i >> 4, q = (i & 15) * 4;
        *(float4*)&Cs[ll][q] = *(const float4*)&xbca[row0 + (size_t)ll * CONVD + h * 64 + q];
    }
    __syncthreads();

    for (int p = m0; p < 64; p += 4) {
        float a = 0.f;
        for (int m = 0; m <= l; m++) a += Gs[l][m] * Cs[m][p];
        ydiag[(size_t)(b * SEQ + c * CHUNK + l) * DMODEL + h * 64 + p] = a;
    }

    if (tid < 64) {
        float a = 0.f;
#pragma unroll 8
        for (int ll = 0; ll < 64; ll++) a += Cs[ll][tid] * Bs[ll][tid];
        cs[(size_t)bid * 64 + tid] = a;
    }
}

// ============================================================================
// Inter-chunk scan (constant decay exp(63*A_log[h]) per head)
// ============================================================================
__global__ void scan_kernel(const float* __restrict__ cs, const float* __restrict__ A_log,
                            float* __restrict__ prev)
{
    int bh = blockIdx.x;     // 0..63 = b*32+h
    int h  = bh & 31;
    int n  = threadIdx.x;    // 0..63
    float d = expf(63.f * A_log[h]);
    float s = 0.f;
    for (int c = 0; c < NCHUNK; c++) {
        size_t idx = ((size_t)bh * NCHUNK + c) * 64 + n;
        prev[idx] = s;
        s = s * d + cs[idx];
    }
}

// ============================================================================
// Y = Y_diag + Y_off (prev . C, broadcast over p); gate with silu(z); RMSNorm.
// One block per row.
// ============================================================================
__global__ __launch_bounds__(256) void combine_kernel(
    const float* __restrict__ ydiag, const float* __restrict__ zxbc,
    const float* __restrict__ xbca,  const float* __restrict__ prev,
    const float* __restrict__ rms_w, float* __restrict__ yn)
{
    int r = blockIdx.x;
    int b = r >> 12;
    int l = r & (SEQ - 1);
    int c = l >> 6;

    __shared__ float sh_yoff[NHEADS];
    __shared__ float sh_red[8];

    int tid = threadIdx.x, warp = tid >> 5, lane = tid & 31;

    for (int h = warp; h < NHEADS; h += 8) {
        const float* Crow = xbca + (size_t)r * CONVD + 2 * DMODEL + h * 64;
        const float* pv   = prev + ((size_t)(b * NHEADS + h) * NCHUNK + c) * 64;
        int n0 = lane * 2;
        float v = Crow[n0] * pv[n0] + Crow[n0 + 1] * pv[n0 + 1];
#pragma unroll
        for (int o = 16; o; o >>= 1) v += __shfl_down_sync(0xffffffffu, v, o);
        if (lane == 0) sh_yoff[h] = v;
    }
    __syncthreads();

    float vals[8];
    float ss = 0.f;
#pragma unroll
    for (int j = 0; j < 8; j++) {
        int d = tid + j * 256;
        float z  = zxbc[(size_t)r * ZXB_LD + d];
        float sz = z / (1.f + expf(-z));
        float y  = (ydiag[(size_t)r * DMODEL + d] + sh_yoff[d >> 6]) * sz;
        vals[j] = y;
        ss += y * y;
    }
#pragma unroll
    for (int o = 16; o; o >>= 1) ss += __shfl_down_sync(0xffffffffu, ss, o);
    if (lane == 0) sh_red[warp] = ss;
    __syncthreads();
    if (tid == 0) {
        float t = 0.f;
#pragma unroll
        for (int w = 0; w < 8; w++) t += sh_red[w];
        sh_red[0] = rsqrtf(t / (float)DMODEL + RMS_EPS);
    }
    __syncthreads();
    float scale = sh_red[0];
#pragma unroll
    for (int j = 0; j < 8; j++) {
        int d = tid + j * 256;
        yn[(size_t)r * DMODEL + d] = vals[j] * scale * rms_w[d];
    }
}

// ============================================================================
// launch
// ============================================================================
extern "C" void kernel_launch(void* const* d_in, const int* in_sizes, int n_in,
                              void* d_out, int out_size)
{
    const float* u      = (const float*)d_in[0];
    const float* W_in   = (const float*)d_in[1];
    const float* W_out  = (const float*)d_in[2];
    const float* conv_w = (const float*)d_in[3];
    const float* conv_b = (const float*)d_in[4];
    const float* A_log  = (const float*)d_in[5];
    const float* rms_w  = (const float*)d_in[6];
    float* out = (float*)d_out;

    float *zxbc, *xbca, *y, *yn, *cs, *prev;
    cudaGetSymbolAddress((void**)&zxbc, g_zxbc);
    cudaGetSymbolAddress((void**)&xbca, g_xbca);
    cudaGetSymbolAddress((void**)&y,    g_y);
    cudaGetSymbolAddress((void**)&yn,   g_yn);
    cudaGetSymbolAddress((void**)&cs,   g_cs);
    cudaGetSymbolAddress((void**)&prev, g_prev);

    // 1) zxbc[:, 0:8192] = u @ W_in^T  (dt columns unused by reference)
    gemm_tn_tf32<<<dim3(ZXB_LD / 128, ROWS / 128), 256>>>(u, W_in, zxbc, ROWS, ZXB_LD, DMODEL);
    // 2) depthwise conv + silu
    conv_silu_kernel<<<dim3(CONVD / 256, ROWS), 256>>>(zxbc, conv_w, conv_b, xbca);
    // 3) per-chunk SSD
    ssd_chunk_kernel<<<BATCH * NHEADS * NCHUNK, 256>>>(xbca, y, cs);
    // 4) inter-chunk scan
    scan_kernel<<<BATCH * NHEADS, 64>>>(cs, A_log, prev);
    // 5) Y_off + gate + rmsnorm
    combine_kernel<<<ROWS, 256>>>(y, zxbc, xbca, prev, rms_w, yn);
    // 6) out = yn @ W_out^T
    gemm_tn_tf32<<<dim3(DMODEL / 128, ROWS / 128), 256>>>(yn, W_out, out, ROWS, DMODEL, DMODEL);
}

// round 3
// speedup vs baseline: 1.2125x; 1.2125x over previous
#include <cuda_runtime.h>
#include <cuda_bf16.h>
#include <math.h>

// ---------------- constants ----------------
#define BATCH   2
#define SEQ     4096
#define ROWS    (BATCH*SEQ)        // 8192
#define DMODEL  2048
#define DSTATE  64
#define DHEAD   64
#define NHEADS  32
#define CHUNK   64
#define NCHUNK  (SEQ/CHUNK)        // 64
#define CONVD   6144               // D_MODEL + 2*N_HEADS*D_STATE
#define ZXB_LD  8192               // cols we compute of zxbcdt (dt cols unused)
#define RMS_EPS 1.1920929e-07f

// ---------------- scratch (device globals: allocation-free) ----------------
__device__ float    g_zxbc[(size_t)ROWS * ZXB_LD];   // GEMM1 out: z | xBC(pre-conv)
__device__ float    g_xbca[(size_t)ROWS * CONVD];    // silu(conv(xBC))
__device__ float    g_y   [(size_t)ROWS * DMODEL];   // Y_diag
__device__ unsigned g_yn  [(size_t)ROWS * DMODEL];   // gated+rmsnormed, tf32 bits
__device__ float    g_cs  [(size_t)BATCH*NHEADS*NCHUNK*DSTATE];
__device__ float    g_prev[(size_t)BATCH*NHEADS*NCHUNK*DSTATE];
__device__ unsigned g_ut  [(size_t)ROWS * DMODEL];   // u in tf32 bits
__device__ unsigned g_wit [(size_t)ZXB_LD * DMODEL]; // W_in rows 0..8191, tf32 bits
__device__ unsigned g_wot [(size_t)DMODEL * DMODEL]; // W_out, tf32 bits

// ---------------- helpers ----------------
__device__ __forceinline__ unsigned f2tf(float x) {
    unsigned r; asm("cvt.rna.tf32.f32 %0, %1;" : "=r"(r) : "f"(x)); return r;
}
__device__ __forceinline__ void cp16(void* dst, const void* src) {
    unsigned saddr = (unsigned)__cvta_generic_to_shared(dst);
    asm volatile("cp.async.cg.shared.global [%0], [%1], 16;" :: "r"(saddr), "l"(src));
}

// elementwise fp32 -> tf32 bits (vectorized)
__global__ void tf32_convert(const float* __restrict__ in, unsigned* __restrict__ out, size_t n4)
{
    size_t i = (size_t)blockIdx.x * blockDim.x + threadIdx.x;
    if (i >= n4) return;
    float4 v = ((const float4*)in)[i];
    uint4 o;
    o.x = f2tf(v.x); o.y = f2tf(v.y); o.z = f2tf(v.z); o.w = f2tf(v.w);
    ((uint4*)out)[i] = o;
}

// ============================================================================
// GEMM: C[M,N] = A[M,K] * B[N,K]^T ; A,B already tf32 bits (u32), row-major.
// Block 128x128, K-tile 32, 256 threads = 8 warps (2m x 4n), warp tile 64x32.
// cp.async double-buffered smem mainloop: no CVT, no STS in the loop.
// ============================================================================
#define SMS (128 * 36)   // one stage of one matrix, in u32
__global__ __launch_bounds__(256) void gemm_tn_tf32(
    const unsigned* __restrict__ A, const unsigned* __restrict__ B,
    float* __restrict__ C, int M, int N, int K)
{
    extern __shared__ unsigned sm[];
    unsigned* AsB = sm;             // [2][SMS]
    unsigned* BsB = sm + 2 * SMS;   // [2][SMS]

    const int tid  = threadIdx.x;
    const int row0 = blockIdx.y * 128;
    const int col0 = blockIdx.x * 128;
    const int warp = tid >> 5, lane = tid & 31;
    const int wm = warp >> 2, wn = warp & 3;
    const int g  = lane >> 2, tg = lane & 3;

    float acc[4][4][4];
#pragma unroll
    for (int i = 0; i < 4; i++)
#pragma unroll
        for (int j = 0; j < 4; j++)
#pragma unroll
            for (int k = 0; k < 4; k++) acc[i][j][k] = 0.f;

    const int lr = tid >> 3;        // 0..31
    const int lc = (tid & 7) * 4;   // u32 col (16B aligned)

    const unsigned* Ag = A + (size_t)(row0 + lr) * K + lc;
    const unsigned* Bg = B + (size_t)(col0 + lr) * K + lc;
    const size_t gstep = (size_t)32 * K;

    const int NT = K >> 5;

    // issue stage t into buffer buf
    auto issue = [&](int t, int buf) {
        unsigned* as = AsB + buf * SMS;
        unsigned* bs = BsB + buf * SMS;
        int ko = t * 32;
#pragma unroll
        for (int s = 0; s < 4; s++) {
            cp16(&as[(s * 32 + lr) * 36 + lc], Ag + ko + s * gstep);
            cp16(&bs[(s * 32 + lr) * 36 + lc], Bg + ko + s * gstep);
        }
        asm volatile("cp.async.commit_group;");
    };

    issue(0, 0);

    for (int t = 0; t < NT; t++) {
        if (t + 1 < NT) {
            issue(t + 1, (t + 1) & 1);
            asm volatile("cp.async.wait_group 1;");
        } else {
            asm volatile("cp.async.wait_group 0;");
        }
        __syncthreads();

        const unsigned* As = AsB + (t & 1) * SMS;
        const unsigned* Bs = BsB + (t & 1) * SMS;

#pragma unroll
        for (int kk = 0; kk < 32; kk += 8) {
            unsigned a[4][4], bf[4][2];
#pragma unroll
            for (int mt = 0; mt < 4; mt++) {
                int r = wm * 64 + mt * 16 + g;
                a[mt][0] = As[r * 36 + kk + tg];
                a[mt][1] = As[(r + 8) * 36 + kk + tg];
                a[mt][2] = As[r * 36 + kk + tg + 4];
                a[mt][3] = As[(r + 8) * 36 + kk + tg + 4];
            }
#pragma unroll
            for (int nt = 0; nt < 4; nt++) {
                int cn = wn * 32 + nt * 8 + g;
                bf[nt][0] = Bs[cn * 36 + kk + tg];
                bf[nt][1] = Bs[cn * 36 + kk + tg + 4];
            }
#pragma unroll
            for (int mt = 0; mt < 4; mt++)
#pragma unroll
                for (int nt = 0; nt < 4; nt++)
                    asm volatile(
                        "mma.sync.aligned.m16n8k8.row.col.f32.tf32.tf32.f32 "
                        "{%0,%1,%2,%3}, {%4,%5,%6,%7}, {%8,%9}, {%0,%1,%2,%3};"
                        : "+f"(acc[mt][nt][0]), "+f"(acc[mt][nt][1]),
                          "+f"(acc[mt][nt][2]), "+f"(acc[mt][nt][3])
                        : "r"(a[mt][0]), "r"(a[mt][1]), "r"(a[mt][2]), "r"(a[mt][3]),
                          "r"(bf[nt][0]), "r"(bf[nt][1]));
        }
        __syncthreads();
    }

#pragma unroll
    for (int mt = 0; mt < 4; mt++) {
        int r = row0 + wm * 64 + mt * 16 + g;
#pragma unroll
        for (int nt = 0; nt < 4; nt++) {
            int cc = col0 + wn * 32 + nt * 8 + 2 * tg;
            *(float2*)&C[(size_t)r * N + cc]       = make_float2(acc[mt][nt][0], acc[mt][nt][1]);
            *(float2*)&C[(size_t)(r + 8) * N + cc] = make_float2(acc[mt][nt][2], acc[mt][nt][3]);
        }
    }
}

// ============================================================================
// Depthwise conv(3) + bias + SiLU over xBC channels (cols 2048..8191 of zxbc)
// ============================================================================
__global__ void conv_silu_kernel(const float* __restrict__ zxbc,
                                 const float* __restrict__ cw,
                                 const float* __restrict__ cb,
                                 float* __restrict__ out)
{
    int ch = blockIdx.x * blockDim.x + threadIdx.x;
    int r  = blockIdx.y;
    if (ch >= CONVD) return;
    int l = r & (SEQ - 1);
    const float* col = zxbc + DMODEL + ch;
    float xm = (l > 0)       ? col[(size_t)(r - 1) * ZXB_LD] : 0.f;
    float x0 =                 col[(size_t)r       * ZXB_LD];
    float xp = (l < SEQ - 1) ? col[(size_t)(r + 1) * ZXB_LD] : 0.f;
    float v = fmaf(cw[ch * 3], xm, fmaf(cw[ch * 3 + 1], x0, fmaf(cw[ch * 3 + 2], xp, cb[ch])));
    out[(size_t)r * CONVD + ch] = v / (1.f + expf(-v));
}

// ============================================================================
// Per-chunk SSD
// ============================================================================
__global__ __launch_bounds__(256) void ssd_chunk_kernel(const float* __restrict__ xbca,
                                                        float* __restrict__ ydiag,
                                                        float* __restrict__ cs)
{
    __shared__ float Bs[64][64];
    __shared__ float Cs[64][64];
    __shared__ float Gs[64][64];

    int bid = blockIdx.x;
    int c  = bid & 63;
    int bh = bid >> 6;
    int h  = bh & 31;
    int b  = bh >> 5;
    size_t row0 = (size_t)(b * SEQ + c * CHUNK) * CONVD;
    int tid = threadIdx.x;

    for (int i = tid; i < 64 * 16; i += 256) {
        int l = i >> 4, q = (i & 15) * 4;
        *(float4*)&Bs[l][q] = *(const float4*)&xbca[row0 + (size_t)l * CONVD + DMODEL + h * 64 + q];
        *(float4*)&Cs[l][q] = *(const float4*)&xbca[row0 + (size_t)l * CONVD + 2 * DMODEL + h * 64 + q];
    }
    __syncthreads();

    int l  = tid >> 2;
    int m0 = tid & 3;
    for (int m = m0; m <= l; m += 4) {
        float a = 0.f;
#pragma unroll 8
        for (int n = 0; n < 64; n++) a += Cs[l][n] * Bs[m][n];
        Gs[l][m] = a;
    }
    __syncthreads();

    for (int i = tid; i < 64 * 16; i += 256) {
        int ll = i >> 4, q = (i & 15) * 4;
        *(float4*)&Cs[ll][q] = *(const float4*)&xbca[row0 + (size_t)ll * CONVD + h * 64 + q];
    }
    __syncthreads();

    for (int p = m0; p < 64; p += 4) {
        float a = 0.f;
        for (int m = 0; m <= l; m++) a += Gs[l][m] * Cs[m][p];
        ydiag[(size_t)(b * SEQ + c * CHUNK + l) * DMODEL + h * 64 + p] = a;
    }

    if (tid < 64) {
        float a = 0.f;
#pragma unroll 8
        for (int ll = 0; ll < 64; ll++) a += Cs[ll][tid] * Bs[ll][tid];
        cs[(size_t)bid * 64 + tid] = a;
    }
}

// ============================================================================
// Inter-chunk scan (constant decay exp(63*A_log[h]) per head)
// ============================================================================
__global__ void scan_kernel(const float* __restrict__ cs, const float* __restrict__ A_log,
                            float* __restrict__ prev)
{
    int bh = blockIdx.x;
    int h  = bh & 31;
    int n  = threadIdx.x;
    float d = expf(63.f * A_log[h]);
    float s = 0.f;
    for (int c = 0; c < NCHUNK; c++) {
        size_t idx = ((size_t)bh * NCHUNK + c) * 64 + n;
        prev[idx] = s;
        s = s * d + cs[idx];
    }
}

// ============================================================================
// Y = Y_diag + Y_off; gate with silu(z); RMSNorm. Output stored as tf32 bits.
// ============================================================================
__global__ __launch_bounds__(256) void combine_kernel(
    const float* __restrict__ ydiag, const float* __restrict__ zxbc,
    const float* __restrict__ xbca,  const float* __restrict__ prev,
    const float* __restrict__ rms_w, unsigned* __restrict__ yn)
{
    int r = blockIdx.x;
    int b = r >> 12;
    int l = r & (SEQ - 1);
    int c = l >> 6;

    __shared__ float sh_yoff[NHEADS];
    __shared__ float sh_red[8];

    int tid = threadIdx.x, warp = tid >> 5, lane = tid & 31;

    for (int h = warp; h < NHEADS; h += 8) {
        const float* Crow = xbca + (size_t)r * CONVD + 2 * DMODEL + h * 64;
        const float* pv   = prev + ((size_t)(b * NHEADS + h) * NCHUNK + c) * 64;
        int n0 = lane * 2;
        float v = Crow[n0] * pv[n0] + Crow[n0 + 1] * pv[n0 + 1];
#pragma unroll
        for (int o = 16; o; o >>= 1) v += __shfl_down_sync(0xffffffffu, v, o);
        if (lane == 0) sh_yoff[h] = v;
    }
    __syncthreads();

    float vals[8];
    float ss = 0.f;
#pragma unroll
    for (int j = 0; j < 8; j++) {
        int d = tid + j * 256;
        float z  = zxbc[(size_t)r * ZXB_LD + d];
        float sz = z / (1.f + expf(-z));
        float y  = (ydiag[(size_t)r * DMODEL + d] + sh_yoff[d >> 6]) * sz;
        vals[j] = y;
        ss += y * y;
    }
#pragma unroll
    for (int o = 16; o; o >>= 1) ss += __shfl_down_sync(0xffffffffu, ss, o);
    if (lane == 0) sh_red[warp] = ss;
    __syncthreads();
    if (tid == 0) {
        float t = 0.f;
#pragma unroll
        for (int w = 0; w < 8; w++) t += sh_red[w];
        sh_red[0] = rsqrtf(t / (float)DMODEL + RMS_EPS);
    }
    __syncthreads();
    float scale = sh_red[0];
#pragma unroll
    for (int j = 0; j < 8; j++) {
        int d = tid + j * 256;
        yn[(size_t)r * DMODEL + d] = f2tf(vals[j] * scale * rms_w[d]);
    }
}

// ============================================================================
// launch
// ============================================================================
extern "C" void kernel_launch(void* const* d_in, const int* in_sizes, int n_in,
                              void* d_out, int out_size)
{
    const float* u      = (const float*)d_in[0];
    const float* W_in   = (const float*)d_in[1];
    const float* W_out  = (const float*)d_in[2];
    const float* conv_w = (const float*)d_in[3];
    const float* conv_b = (const float*)d_in[4];
    const float* A_log  = (const float*)d_in[5];
    const float* rms_w  = (const float*)d_in[6];
    float* out = (float*)d_out;

    float *zxbc, *xbca, *y, *cs, *prev;
    unsigned *yn, *ut, *wit, *wot;
    cudaGetSymbolAddress((void**)&zxbc, g_zxbc);
    cudaGetSymbolAddress((void**)&xbca, g_xbca);
    cudaGetSymbolAddress((void**)&y,    g_y);
    cudaGetSymbolAddress((void**)&yn,   g_yn);
    cudaGetSymbolAddress((void**)&cs,   g_cs);
    cudaGetSymbolAddress((void**)&prev, g_prev);
    cudaGetSymbolAddress((void**)&ut,   g_ut);
    cudaGetSymbolAddress((void**)&wit,  g_wit);
    cudaGetSymbolAddress((void**)&wot,  g_wot);

    static bool attr_done = false;
    if (!attr_done) {
        cudaFuncSetAttribute(gemm_tn_tf32, cudaFuncAttributeMaxDynamicSharedMemorySize, 4 * SMS * 4);
        attr_done = true;
    }
    const size_t smem = 4 * SMS * 4;   // 73728 B

    // 0) convert operands to tf32 bits
    {
        size_t n4u = (size_t)ROWS * DMODEL / 4;
        tf32_convert<<<(unsigned)((n4u + 255) / 256), 256>>>(u, ut, n4u);
        size_t n4w = (size_t)ZXB_LD * DMODEL / 4;
        tf32_convert<<<(unsigned)((n4w + 255) / 256), 256>>>(W_in, wit, n4w);
        size_t n4o = (size_t)DMODEL * DMODEL / 4;
        tf32_convert<<<(unsigned)((n4o + 255) / 256), 256>>>(W_out, wot, n4o);
    }
    // 1) zxbc = u @ W_in^T (first 8192 output cols)
    gemm_tn_tf32<<<dim3(ZXB_LD / 128, ROWS / 128), 256, smem>>>(ut, wit, zxbc, ROWS, ZXB_LD, DMODEL);
    // 2) depthwise conv + silu
    conv_silu_kernel<<<dim3(CONVD / 256, ROWS), 256>>>(zxbc, conv_w, conv_b, xbca);
    // 3) per-chunk SSD
    ssd_chunk_kernel<<<BATCH * NHEADS * NCHUNK, 256>>>(xbca, y, cs);
    // 4) inter-chunk scan
    scan_kernel<<<BATCH * NHEADS, 64>>>(cs, A_log, prev);
    // 5) Y_off + gate + rmsnorm (writes tf32 bits)
    combine_kernel<<<ROWS, 256>>>(y, zxbc, xbca, prev, rms_w, yn);
    // 6) out = yn @ W_out^T
    gemm_tn_tf32<<<dim3(DMODEL / 128, ROWS / 128), 256, smem>>>(yn, wot, out, ROWS, DMODEL, DMODEL);
}